// round 11
// baseline (speedup 1.0000x reference)
#include <cuda_runtime.h>
#include <cuda_fp16.h>
#include <math.h>

// Problem constants
#define BATCH 2
#define SEQ   2048
#define EMBD  1024
#define NHEAD 16
#define HDIM  64
#define BT    (BATCH*SEQ)          // 4096
#define QKVN  (3*EMBD)             // 3072
#define LOG2E 1.4426950408889634f

// ---------------- scratch (device globals) ----------------
__device__ __half g_xh[BT * EMBD];                       // x in half
__device__ __half g_wqkvt[QKVN * EMBD];                  // Wqkv^T [3072][1024] half
__device__ __half g_wprojt[EMBD * EMBD];                 // Wproj^T [1024][1024] half
__device__ __half g_qh[BATCH * NHEAD * SEQ * HDIM];      // [bh][t][d]  (q PRESCALED by 0.125)
__device__ __half g_kh[BATCH * NHEAD * SEQ * HDIM];      // [bh][t][d]
__device__ __half g_vh[BATCH * NHEAD * SEQ * HDIM];      // [bh][t][d]
__device__ __half g_atth[BT * EMBD];                     // attention out, half

// ---------------- helpers ----------------
__device__ __forceinline__ unsigned packh2(float a, float b) {
    __half2 h = __floats2half2_rn(a, b);
    return *(unsigned*)&h;
}

__device__ __forceinline__ void mma16(float* c,
    unsigned a0, unsigned a1, unsigned a2, unsigned a3,
    unsigned b0, unsigned b1)
{
    asm volatile(
        "mma.sync.aligned.m16n8k16.row.col.f32.f16.f16.f32 "
        "{%0,%1,%2,%3},{%4,%5,%6,%7},{%8,%9},{%0,%1,%2,%3};"
        : "+f"(c[0]), "+f"(c[1]), "+f"(c[2]), "+f"(c[3])
        : "r"(a0), "r"(a1), "r"(a2), "r"(a3), "r"(b0), "r"(b1));
}

__device__ __forceinline__ void ldsm4(unsigned& r0, unsigned& r1,
                                      unsigned& r2, unsigned& r3,
                                      const __half* p)
{
    unsigned a = (unsigned)__cvta_generic_to_shared(p);
    asm volatile("ldmatrix.sync.aligned.m8n8.x4.shared.b16 {%0,%1,%2,%3}, [%4];"
        : "=r"(r0), "=r"(r1), "=r"(r2), "=r"(r3) : "r"(a));
}

__device__ __forceinline__ void ldsm4t(unsigned& r0, unsigned& r1,
                                       unsigned& r2, unsigned& r3,
                                       const __half* p)
{
    unsigned a = (unsigned)__cvta_generic_to_shared(p);
    asm volatile("ldmatrix.sync.aligned.m8n8.x4.trans.shared.b16 {%0,%1,%2,%3}, [%4];"
        : "=r"(r0), "=r"(r1), "=r"(r2), "=r"(r3) : "r"(a));
}

// 2^t via FMA-pipe polynomial (no MUFU).
__device__ __forceinline__ float exp2_poly(float t) {
    t = fmaxf(t, -126.0f);
    float z = t + 12582912.0f;
    int   ei = __float_as_int(z) - 0x4B400000;
    float f = t - (float)ei;
    float p = 1.3333558e-3f;
    p = fmaf(p, f, 9.6181291e-3f);
    p = fmaf(p, f, 5.5504109e-2f);
    p = fmaf(p, f, 2.4022651e-1f);
    p = fmaf(p, f, 6.9314718e-1f);
    p = fmaf(p, f, 1.0f);
    return __int_as_float(__float_as_int(p) + (ei << 23));
}

__device__ __forceinline__ void cpa16(__half* dst_smem, const __half* src_gmem) {
    unsigned d = (unsigned)__cvta_generic_to_shared(dst_smem);
    asm volatile("cp.async.cg.shared.global [%0], [%1], 16;" :: "r"(d), "l"(src_gmem));
}
#define CP_COMMIT() asm volatile("cp.async.commit_group;")
#define CP_WAIT0()  asm volatile("cp.async.wait_group 0;" ::: "memory")
#define CP_WAIT1()  asm volatile("cp.async.wait_group 1;" ::: "memory")

// ---------------- mbarrier helpers ----------------
__device__ __forceinline__ void mbar_init(unsigned addr, unsigned count) {
    asm volatile("mbarrier.init.shared.b64 [%0], %1;" :: "r"(addr), "r"(count) : "memory");
}
__device__ __forceinline__ void mbar_arrive(unsigned addr) {
    asm volatile("mbarrier.arrive.shared.b64 _, [%0];" :: "r"(addr) : "memory");
}
__device__ __forceinline__ void cpam_arrive(unsigned addr) {
    asm volatile("cp.async.mbarrier.arrive.noinc.shared.b64 [%0];" :: "r"(addr) : "memory");
}
__device__ __forceinline__ void mbar_wait(unsigned addr, unsigned parity) {
    unsigned done;
    asm volatile(
        "{\n\t.reg .pred p;\n\t"
        "mbarrier.try_wait.parity.acquire.cta.shared::cta.b64 p, [%1], %2;\n\t"
        "selp.b32 %0, 1, 0, p;\n\t}"
        : "=r"(done) : "r"(addr), "r"(parity) : "memory");
    if (!done) {
        asm volatile(
            "{\n\t.reg .pred P1;\n\t"
            "WL_%=:\n\t"
            "mbarrier.try_wait.parity.acquire.cta.shared::cta.b64 P1, [%0], %1, 0x989680;\n\t"
            "@P1 bra WD_%=;\n\t"
            "bra WL_%=;\n\t"
            "WD_%=:\n\t}"
            :: "r"(addr), "r"(parity) : "memory");
    }
}

// ---------------- fused prepass: conv x -> half, transpose both weights ---------
__global__ __launch_bounds__(256) void prep(
    const float* __restrict__ x,
    const float* __restrict__ Wqkv, const float* __restrict__ Wproj)
{
    __shared__ __half tile[32][33];
    const int bid = blockIdx.x;
    const int tid = threadIdx.x;

    if (bid < 4096) {
        int i = bid * 256 + tid;
        float4 v = *(const float4*)(x + (size_t)i * 4);
        *(uint2*)(g_xh + (size_t)i * 4) = make_uint2(packh2(v.x, v.y), packh2(v.z, v.w));
        return;
    }

    const float* in;
    __half* out;
    int K, N, n0, k0;
    if (bid < 4096 + 3072) {
        int b = bid - 4096;
        in = Wqkv; out = g_wqkvt; K = EMBD; N = QKVN;
        n0 = (b % 96) * 32; k0 = (b / 96) * 32;
    } else {
        int b = bid - 7168;
        in = Wproj; out = g_wprojt; K = EMBD; N = EMBD;
        n0 = (b % 32) * 32; k0 = (b / 32) * 32;
    }
    const int tx = tid & 31;
    const int ty = tid >> 5;
#pragma unroll
    for (int j = 0; j < 4; j++) {
        int kr = ty + j * 8;
        tile[kr][tx] = __float2half(in[(size_t)(k0 + kr) * N + n0 + tx]);
    }
    __syncthreads();
#pragma unroll
    for (int j = 0; j < 4; j++) {
        int nr = ty + j * 8;
        out[(size_t)(n0 + nr) * K + k0 + tx] = tile[tx][nr];
    }
}

// ================= GEMM mainloop: 3-stage cp.async, f32 accum (R9) ==============
#define GP 72
#define GSTAGE (128 * GP)

#define GEMM_STAGE(s_, k0_) do {                                                \
    __half* As_ = smg + (2 * (s_)) * GSTAGE;                                    \
    __half* Bs_ = smg + (2 * (s_) + 1) * GSTAGE;                                \
    _Pragma("unroll")                                                           \
    for (int it_ = 0; it_ < 4; it_++) {                                         \
        int c_ = tid + it_ * 256;                                               \
        int r_ = c_ >> 3;                                                       \
        int o8_ = (c_ & 7) << 3;                                                \
        cpa16(As_ + r_ * GP + o8_, A + (size_t)(m0 + r_) * EMBD + (k0_) + o8_); \
        cpa16(Bs_ + r_ * GP + o8_, Bt + (size_t)(n0 + r_) * EMBD + (k0_) + o8_);\
    }                                                                           \
    CP_COMMIT();                                                                \
} while (0)

#define GEMM_MAINLOOP()                                                         \
    const int tid  = threadIdx.x;                                               \
    const int w    = tid >> 5;                                                  \
    const int lane = tid & 31;                                                  \
    const int grp  = lane >> 2;                                                 \
    const int t4   = lane & 3;                                                  \
    const int mw   = (w >> 1) * 32;                                             \
    const int nw   = (w & 1) * 64;                                              \
    const int m0   = blockIdx.y * 128;                                          \
    const int n0   = blockIdx.x * 128;                                          \
    const int arow = lane & 15;                                                 \
    const int acol = (lane >> 4) << 3;                                          \
    const int brow = (lane & 7) + ((lane >> 4) << 3);                           \
    const int bcol = ((lane >> 3) & 1) << 3;                                    \
    float acc[2][8][4];                                                         \
    _Pragma("unroll")                                                           \
    for (int mf = 0; mf < 2; mf++)                                              \
        _Pragma("unroll")                                                       \
        for (int nc = 0; nc < 8; nc++)                                          \
            _Pragma("unroll")                                                   \
            for (int j = 0; j < 4; j++) acc[mf][nc][j] = 0.f;                   \
    const int nk = EMBD / 64;                                                   \
    GEMM_STAGE(0, 0);                                                           \
    GEMM_STAGE(1, 64);                                                          \
    for (int i = 0; i < nk; i++) {                                              \
        if (i + 1 < nk) CP_WAIT1(); else CP_WAIT0();                            \
        __syncthreads();                                                        \
        if (i + 2 < nk) { int s_ = (i + 2) % 3; GEMM_STAGE(s_, (i + 2) * 64); } \
        const __half* Ac = smg + (2 * (i % 3)) * GSTAGE;                        \
        const __half* Bc = smg + (2 * (i % 3) + 1) * GSTAGE;                    \
        _Pragma("unroll")                                                       \
        for (int ks = 0; ks < 4; ks++) {                                        \
            unsigned a[2][4];                                                   \
            unsigned bq[2][4];                                                  \
            ldsm4(a[0][0], a[0][1], a[0][2], a[0][3],                           \
                  Ac + (mw + arow) * GP + ks * 16 + acol);                      \
            ldsm4(a[1][0], a[1][1], a[1][2], a[1][3],                           \
                  Ac + (mw + 16 + arow) * GP + ks * 16 + acol);                 \
            ldsm4(bq[0][0], bq[0][1], bq[0][2], bq[0][3],                       \
                  Bc + (nw + brow) * GP + ks * 16 + bcol);                      \
            _Pragma("unroll")                                                   \
            for (int p = 0; p < 4; p++) {                                       \
                if (p < 3)                                                      \
                    ldsm4(bq[(p + 1) & 1][0], bq[(p + 1) & 1][1],               \
                          bq[(p + 1) & 1][2], bq[(p + 1) & 1][3],               \
                          Bc + (nw + (p + 1) * 16 + brow) * GP + ks * 16 + bcol); \
                unsigned* bb = bq[p & 1];                                       \
                mma16(acc[0][2 * p],     a[0][0], a[0][1], a[0][2], a[0][3], bb[0], bb[1]); \
                mma16(acc[1][2 * p],     a[1][0], a[1][1], a[1][2], a[1][3], bb[0], bb[1]); \
                mma16(acc[0][2 * p + 1], a[0][0], a[0][1], a[0][2], a[0][3], bb[2], bb[3]); \
                mma16(acc[1][2 * p + 1], a[1][0], a[1][1], a[1][2], a[1][3], bb[2], bb[3]); \
            }                                                                   \
        }                                                                       \
    }

#define GSMEM (6 * GSTAGE * (int)sizeof(__half))   // 110592 B

// ---------------- QKV GEMM with fused bias + RoPE + scatter epilogue ------------
__global__ __launch_bounds__(256, 2) void gemm_qkv(
    const __half* __restrict__ A, const __half* __restrict__ Bt,
    const float* __restrict__ bias,
    const float* __restrict__ cosb, const float* __restrict__ sinb)
{
    extern __shared__ __half smg[];
    GEMM_MAINLOOP()

    const int region = n0 >> 10;                 // 0=q, 1=k, 2=v
    const int ccbase = (n0 & 1023) + nw;
    __half* dst = (region == 0) ? g_qh : (region == 1) ? g_kh : g_vh;
    const float rsc = (region == 0) ? 0.125f : 1.0f;

#pragma unroll
    for (int mf = 0; mf < 2; mf++) {
#pragma unroll
        for (int hh = 0; hh < 2; hh++) {
            int m = m0 + mw + mf * 16 + hh * 8 + grp;
            int t = m & (SEQ - 1);
            int b = m >> 11;
#pragma unroll
            for (int nc = 0; nc < 8; nc++) {
                int cc = ccbase + nc * 8 + 2 * t4;
                float v0 = acc[mf][nc][2 * hh]     + bias[region * 1024 + cc];
                float v1 = acc[mf][nc][2 * hh + 1] + bias[region * 1024 + cc + 1];
                int hd = cc >> 6;
                int d  = cc & 63;
                size_t o = ((size_t)((b * NHEAD + hd) * SEQ + t)) * HDIM + d;
                if (region < 2) {
                    float c = cosb[t * 32 + (d >> 1)] * rsc;
                    float s = sinb[t * 32 + (d >> 1)] * rsc;
                    *(unsigned*)(dst + o) = packh2(v0 * c - v1 * s, v0 * s + v1 * c);
                } else {
                    *(unsigned*)(dst + o) = packh2(v0, v1);
                }
            }
        }
    }
}

// ---------------- proj GEMM: bias + f32 output ----------------
__global__ __launch_bounds__(256, 2) void gemm_proj(
    const __half* __restrict__ A, const __half* __restrict__ Bt,
    const float* __restrict__ bias, float* __restrict__ C)
{
    extern __shared__ __half smg[];
    GEMM_MAINLOOP()

#pragma unroll
    for (int mf = 0; mf < 2; mf++) {
#pragma unroll
        for (int hh = 0; hh < 2; hh++) {
            int m = m0 + mw + mf * 16 + hh * 8 + grp;
            float* crow = C + (size_t)m * EMBD + n0 + nw;
#pragma unroll
            for (int nc = 0; nc < 8; nc++) {
                int c = nc * 8 + 2 * t4;
                float2 o;
                o.x = acc[mf][nc][2 * hh]     + bias[n0 + nw + c];
                o.y = acc[mf][nc][2 * hh + 1] + bias[n0 + nw + c + 1];
                *(float2*)(crow + c) = o;
            }
        }
    }
}

// ---------------- flash attention: mbarrier-desynchronized 3-stage ring ---------
// 8 warps x 16 rows; warps drift up to ~2 tiles so softmax (FMA pipe) of one warp
// overlaps QK/PV mma (tensor pipe) of another. full[s]: cp.async-armed, count 256.
// empty[s]: one arrive per warp, count 8.
#define AP 72

__global__ __launch_bounds__(256, 2) void attn_h()
{
    extern __shared__ char smc_a[];
    const unsigned mb = (unsigned)__cvta_generic_to_shared(smc_a);
    __half* Qs  = (__half*)(smc_a + 128);    // 128*72 halfs
    __half* Kb0 = Qs + 128 * AP;             // 3 x 64*72
    __half* Vb0 = Kb0 + 3 * 64 * AP;         // 3 x 64*72

    const int qt = (int)gridDim.x - 1 - (int)blockIdx.x;
    const int bh = blockIdx.y;
    const int b  = bh >> 4;
    const int h  = bh & 15;
    const __half* qp = g_qh + (size_t)bh * SEQ * HDIM;
    const __half* kp = g_kh + (size_t)bh * SEQ * HDIM;
    const __half* vp = g_vh + (size_t)bh * SEQ * HDIM;
    const int q0 = qt * 128;

    const int tid  = threadIdx.x;
    const int w    = tid >> 5;
    const int lane = tid & 31;
    const int grp  = lane >> 2;
    const int t4   = lane & 3;
    const int mw   = w * 16;

    const int arow = lane & 15;
    const int acol = (lane >> 4) << 3;
    const int brow = (lane & 7) + ((lane >> 4) << 3);
    const int bcol = ((lane >> 3) & 1) << 3;

    // barriers: full[s] @ mb + 8s, empty[s] @ mb + 24 + 8s
    if (tid == 0) {
#pragma unroll
        for (int s = 0; s < 3; s++) {
            mbar_init(mb + 8 * s, 256);       // full: every thread's cp.asyncs
            mbar_init(mb + 24 + 8 * s, 8);    // empty: one arrive per warp
        }
    }
    __syncthreads();

    // stage helper (lambda-style macro): stage tile at key base k0_ into ring slot s_
#define KV_STAGE_MB(s_, k0_) do {                                              \
        __half* Kn_ = Kb0 + (s_) * 64 * AP;                                    \
        __half* Vn_ = Vb0 + (s_) * 64 * AP;                                    \
        _Pragma("unroll")                                                      \
        for (int it_ = 0; it_ < 2; it_++) {                                    \
            int slot_ = tid + it_ * 256;                                       \
            int r_  = slot_ >> 3;                                              \
            int c8_ = (slot_ & 7) << 3;                                        \
            cpa16(Kn_ + r_ * AP + c8_, kp + (size_t)((k0_) + r_) * HDIM + c8_);\
            cpa16(Vn_ + r_ * AP + c8_, vp + (size_t)((k0_) + r_) * HDIM + c8_);\
        }                                                                      \
        cpam_arrive(mb + 8 * (s_));                                            \
    } while (0)

    // prologue: Q copies first (covered by stage-0's arrive), then tiles 0,1
#pragma unroll
    for (int it = 0; it < 4; it++) {
        int slot = tid + it * 256;
        int r  = slot >> 3;
        int c8 = (slot & 7) << 3;
        cpa16(Qs + r * AP + c8, qp + (size_t)(q0 + r) * HDIM + c8);
    }
    KV_STAGE_MB(0, 0);
    const int kt_max = 2 * qt + 1;
    if (kt_max >= 1) KV_STAGE_MB(1, 64);

    float O[8][4];
#pragma unroll
    for (int nc = 0; nc < 8; nc++)
#pragma unroll
        for (int j = 0; j < 4; j++) O[nc][j] = 0.f;
    float mrow[2] = {-INFINITY, -INFINITY};
    float lrow[2] = {0.f, 0.f};

    unsigned qa[4][4];
    const int rmax = q0 + mw + 15;

    for (int kt = 0; kt <= kt_max; kt++) {
        const int k0 = kt * 64;

        // produce tile kt+2 (ring slot free once all warps consumed tile kt-1)
        if (kt + 2 <= kt_max) {
            const int s2 = (kt + 2) % 3;
            const int j2 = (kt + 2) / 3;
            if (j2 > 0) mbar_wait(mb + 24 + 8 * s2, (unsigned)((j2 - 1) & 1));
            KV_STAGE_MB(s2, (kt + 2) * 64);
        }

        const int s = kt % 3;
        mbar_wait(mb + 8 * s, (unsigned)((kt / 3) & 1));

        if (kt == 0) {
#pragma unroll
            for (int ks = 0; ks < 4; ks++)
                ldsm4(qa[ks][0], qa[ks][1], qa[ks][2], qa[ks][3],
                      Qs + (mw + arow) * AP + ks * 16 + acol);
        }

        if (k0 <= rmax) {
            const __half* Kb = Kb0 + s * 64 * AP;
            const __half* Vb = Vb0 + s * 64 * AP;

            float S[8][4];
#pragma unroll
            for (int nc = 0; nc < 8; nc++)
#pragma unroll
                for (int j = 0; j < 4; j++) S[nc][j] = 0.f;

#pragma unroll
            for (int ks = 0; ks < 4; ks++) {
#pragma unroll
                for (int nc0 = 0; nc0 < 8; nc0 += 2) {
                    if (k0 + nc0 * 8 <= rmax) {
                        unsigned b0, b1, b2, b3;
                        ldsm4(b0, b1, b2, b3, Kb + (nc0 * 8 + brow) * AP + ks * 16 + bcol);
                        mma16(S[nc0],     qa[ks][0], qa[ks][1], qa[ks][2], qa[ks][3], b0, b1);
                        mma16(S[nc0 + 1], qa[ks][0], qa[ks][1], qa[ks][2], qa[ks][3], b2, b3);
                    }
                }
            }

            if (k0 + 63 > q0 + mw) {
                int r0g = q0 + mw + grp;
                int r1g = r0g + 8;
#pragma unroll
                for (int nc = 0; nc < 8; nc++) {
                    int col = k0 + nc * 8 + 2 * t4;
                    if (col     > r0g) S[nc][0] = -INFINITY;
                    if (col + 1 > r0g) S[nc][1] = -INFINITY;
                    if (col     > r1g) S[nc][2] = -INFINITY;
                    if (col + 1 > r1g) S[nc][3] = -INFINITY;
                }
            }

#pragma unroll
            for (int hh = 0; hh < 2; hh++) {
                float mx = -INFINITY;
#pragma unroll
                for (int nc = 0; nc < 8; nc++)
                    mx = fmaxf(mx, fmaxf(S[nc][2 * hh], S[nc][2 * hh + 1]));
                mx = fmaxf(mx, __shfl_xor_sync(0xffffffffu, mx, 1));
                mx = fmaxf(mx, __shfl_xor_sync(0xffffffffu, mx, 2));

                float mold = mrow[hh];
                float mnew = fmaxf(mold, mx);
                float al   = exp2_poly((mold - mnew) * LOG2E);
                mrow[hh] = mnew;
                float mbv = mnew * LOG2E;

                float sum = 0.f;
#pragma unroll
                for (int nc = 0; nc < 8; nc++) {
                    float p0 = exp2_poly(fmaf(S[nc][2 * hh],     LOG2E, -mbv));
                    float p1 = exp2_poly(fmaf(S[nc][2 * hh + 1], LOG2E, -mbv));
                    S[nc][2 * hh]     = p0;
                    S[nc][2 * hh + 1] = p1;
                    sum += p0 + p1;
                }
                sum += __shfl_xor_sync(0xffffffffu, sum, 1);
                sum += __shfl_xor_sync(0xffffffffu, sum, 2);
                lrow[hh] = lrow[hh] * al + sum;

#pragma unroll
                for (int nc = 0; nc < 8; nc++) {
                    O[nc][2 * hh]     *= al;
                    O[nc][2 * hh + 1] *= al;
                }
            }

#pragma unroll
            for (int ks = 0; ks < 4; ks++) {
                if (k0 + ks * 16 <= rmax) {
                    unsigned a0 = packh2(S[2 * ks][0],     S[2 * ks][1]);
                    unsigned a1 = packh2(S[2 * ks][2],     S[2 * ks][3]);
                    unsigned a2 = packh2(S[2 * ks + 1][0], S[2 * ks + 1][1]);
                    unsigned a3 = packh2(S[2 * ks + 1][2], S[2 * ks + 1][3]);
#pragma unroll
                    for (int nc0 = 0; nc0 < 8; nc0 += 2) {
                        unsigned b0, b1, b2, b3;
                        ldsm4t(b0, b1, b2, b3,
                               Vb + (ks * 16 + arow) * AP + nc0 * 8 + acol);
                        mma16(O[nc0],     a0, a1, a2, a3, b0, b1);
                        mma16(O[nc0 + 1], a0, a1, a2, a3, b2, b3);
                    }
                }
            }
        }

        // warp done with ring slot s
        if (lane == 0) mbar_arrive(mb + 24 + 8 * s);
    }

    // epilogue (per-warp independent; no final sync needed)
#pragma unroll
    for (int hh = 0; hh < 2; hh++) {
        float inv = 1.f / lrow[hh];
        int row = q0 + mw + hh * 8 + grp;
        size_t base = ((size_t)(b * SEQ + row)) * EMBD + h * HDIM;
#pragma unroll
        for (int nc = 0; nc < 8; nc++) {
            int c = nc * 8 + 2 * t4;
            *(unsigned*)(g_atth + base + c) =
                packh2(O[nc][2 * hh] * inv, O[nc][2 * hh + 1] * inv);
        }
    }
#undef KV_STAGE_MB
}

// ---------------- launcher ----------------
extern "C" void kernel_launch(void* const* d_in, const int* in_sizes, int n_in,
                              void* d_out, int out_size)
{
    const float* x     = (const float*)d_in[0];
    const float* Wqkv  = (const float*)d_in[1];
    const float* bqkv  = (const float*)d_in[2];
    const float* Wproj = (const float*)d_in[3];
    const float* bproj = (const float*)d_in[4];
    const float* cosb  = (const float*)d_in[5];
    const float* sinb  = (const float*)d_in[6];
    float* out = (float*)d_out;

    void *p_xh, *p_wqkvt, *p_wprojt, *p_atth;
    cudaGetSymbolAddress(&p_xh, g_xh);
    cudaGetSymbolAddress(&p_wqkvt, g_wqkvt);
    cudaGetSymbolAddress(&p_wprojt, g_wprojt);
    cudaGetSymbolAddress(&p_atth, g_atth);

    // 0) fused prepass: conv x + transpose both weights
    prep<<<8192, 256>>>(x, Wqkv, Wproj);

    cudaFuncSetAttribute(gemm_qkv, cudaFuncAttributeMaxDynamicSharedMemorySize, GSMEM);
    cudaFuncSetAttribute(gemm_proj, cudaFuncAttributeMaxDynamicSharedMemorySize, GSMEM);

    // 1) QKV GEMM with fused bias + RoPE (+Q prescale) epilogue
    gemm_qkv<<<dim3(QKVN / 128, BT / 128), 256, GSMEM>>>(
        (const __half*)p_xh, (const __half*)p_wqkvt, bqkv, cosb, sinb);

    // 2) causal flash attention (mbarrier-desynchronized ring)
    const int asm_bytes = 128 + (128 * AP + 6 * 64 * AP) * (int)sizeof(__half);  // 73856
    cudaFuncSetAttribute(attn_h, cudaFuncAttributeMaxDynamicSharedMemorySize, asm_bytes);
    attn_h<<<dim3(SEQ / 128, BATCH * NHEAD), 256, asm_bytes>>>();

    // 3) output projection
    gemm_proj<<<dim3(EMBD / 128, BT / 128), 256, GSMEM>>>(
        (const __half*)p_atth, (const __half*)p_wprojt, bproj, out);
}

// round 13
// speedup vs baseline: 1.5487x; 1.5487x over previous
#include <cuda_runtime.h>
#include <cuda_fp16.h>
#include <math.h>

// Problem constants
#define BATCH 2
#define SEQ   2048
#define EMBD  1024
#define NHEAD 16
#define HDIM  64
#define BT    (BATCH*SEQ)          // 4096
#define QKVN  (3*EMBD)             // 3072
#define LOG2E 1.4426950408889634f

// ---------------- scratch (device globals) ----------------
__device__ __half g_xh[BT * EMBD];                       // x in half
__device__ __half g_wqkvt[QKVN * EMBD];                  // Wqkv^T [3072][1024] half
__device__ __half g_wprojt[EMBD * EMBD];                 // Wproj^T [1024][1024] half
__device__ __half g_qh[BATCH * NHEAD * SEQ * HDIM];      // [bh][t][d]  (q PRESCALED by 0.125)
__device__ __half g_kh[BATCH * NHEAD * SEQ * HDIM];      // [bh][t][d]
__device__ __half g_vh[BATCH * NHEAD * SEQ * HDIM];      // [bh][t][d]
__device__ __half g_atth[BT * EMBD];                     // attention out, half

// ---------------- helpers ----------------
__device__ __forceinline__ unsigned packh2(float a, float b) {
    __half2 h = __floats2half2_rn(a, b);
    return *(unsigned*)&h;
}

__device__ __forceinline__ void mma16(float* c,
    unsigned a0, unsigned a1, unsigned a2, unsigned a3,
    unsigned b0, unsigned b1)
{
    asm volatile(
        "mma.sync.aligned.m16n8k16.row.col.f32.f16.f16.f32 "
        "{%0,%1,%2,%3},{%4,%5,%6,%7},{%8,%9},{%0,%1,%2,%3};"
        : "+f"(c[0]), "+f"(c[1]), "+f"(c[2]), "+f"(c[3])
        : "r"(a0), "r"(a1), "r"(a2), "r"(a3), "r"(b0), "r"(b1));
}

__device__ __forceinline__ void ldsm4(unsigned& r0, unsigned& r1,
                                      unsigned& r2, unsigned& r3,
                                      const __half* p)
{
    unsigned a = (unsigned)__cvta_generic_to_shared(p);
    asm volatile("ldmatrix.sync.aligned.m8n8.x4.shared.b16 {%0,%1,%2,%3}, [%4];"
        : "=r"(r0), "=r"(r1), "=r"(r2), "=r"(r3) : "r"(a));
}

__device__ __forceinline__ void ldsm4t(unsigned& r0, unsigned& r1,
                                       unsigned& r2, unsigned& r3,
                                       const __half* p)
{
    unsigned a = (unsigned)__cvta_generic_to_shared(p);
    asm volatile("ldmatrix.sync.aligned.m8n8.x4.trans.shared.b16 {%0,%1,%2,%3}, [%4];"
        : "=r"(r0), "=r"(r1), "=r"(r2), "=r"(r3) : "r"(a));
}

// 2^t via FMA-pipe polynomial (no MUFU).
__device__ __forceinline__ float exp2_poly(float t) {
    t = fmaxf(t, -126.0f);
    float z = t + 12582912.0f;
    int   ei = __float_as_int(z) - 0x4B400000;
    float f = t - (float)ei;
    float p = 1.3333558e-3f;
    p = fmaf(p, f, 9.6181291e-3f);
    p = fmaf(p, f, 5.5504109e-2f);
    p = fmaf(p, f, 2.4022651e-1f);
    p = fmaf(p, f, 6.9314718e-1f);
    p = fmaf(p, f, 1.0f);
    return __int_as_float(__float_as_int(p) + (ei << 23));
}

__device__ __forceinline__ void cpa16(__half* dst_smem, const __half* src_gmem) {
    unsigned d = (unsigned)__cvta_generic_to_shared(dst_smem);
    asm volatile("cp.async.cg.shared.global [%0], [%1], 16;" :: "r"(d), "l"(src_gmem));
}
#define CP_COMMIT() asm volatile("cp.async.commit_group;")
#define CP_WAIT0()  asm volatile("cp.async.wait_group 0;" ::: "memory")
#define CP_WAIT1()  asm volatile("cp.async.wait_group 1;" ::: "memory")

// ---------------- fused prepass: conv x -> half, transpose both weights ---------
// 1D grid: [0,4096) conv x ; [4096,7168) Wqkv^T ; [7168,8192) Wproj^T
__global__ __launch_bounds__(256) void prep(
    const float* __restrict__ x,
    const float* __restrict__ Wqkv, const float* __restrict__ Wproj)
{
    __shared__ __half tile[32][33];
    const int bid = blockIdx.x;
    const int tid = threadIdx.x;

    if (bid < 4096) {
        int i = bid * 256 + tid;
        float4 v = *(const float4*)(x + (size_t)i * 4);
        *(uint2*)(g_xh + (size_t)i * 4) = make_uint2(packh2(v.x, v.y), packh2(v.z, v.w));
        return;
    }

    const float* in;
    __half* out;
    int K, N, n0, k0;
    if (bid < 4096 + 3072) {
        int b = bid - 4096;
        in = Wqkv; out = g_wqkvt; K = EMBD; N = QKVN;
        n0 = (b % 96) * 32; k0 = (b / 96) * 32;
    } else {
        int b = bid - 7168;
        in = Wproj; out = g_wprojt; K = EMBD; N = EMBD;
        n0 = (b % 32) * 32; k0 = (b / 32) * 32;
    }
    const int tx = tid & 31;
    const int ty = tid >> 5;
#pragma unroll
    for (int j = 0; j < 4; j++) {
        int kr = ty + j * 8;
        tile[kr][tx] = __float2half(in[(size_t)(k0 + kr) * N + n0 + tx]);
    }
    __syncthreads();
#pragma unroll
    for (int j = 0; j < 4; j++) {
        int nr = ty + j * 8;
        out[(size_t)(n0 + nr) * K + k0 + tx] = tile[tx][nr];
    }
}

// ================= GEMM mainloop: 3-stage cp.async, B-frag prefetch (R9) ========
#define GP 72                      // smem pitch (halfs): 144B rows, conflict-free
#define GSTAGE (128 * GP)          // halfs per tile buffer

#define GEMM_STAGE(s_, k0_) do {                                                \
    __half* As_ = smg + (2 * (s_)) * GSTAGE;                                    \
    __half* Bs_ = smg + (2 * (s_) + 1) * GSTAGE;                                \
    _Pragma("unroll")                                                           \
    for (int it_ = 0; it_ < 4; it_++) {                                         \
        int c_ = tid + it_ * 256;                                               \
        int r_ = c_ >> 3;                                                       \
        int o8_ = (c_ & 7) << 3;                                                \
        cpa16(As_ + r_ * GP + o8_, A + (size_t)(m0 + r_) * EMBD + (k0_) + o8_); \
        cpa16(Bs_ + r_ * GP + o8_, Bt + (size_t)(n0 + r_) * EMBD + (k0_) + o8_);\
    }                                                                           \
    CP_COMMIT();                                                                \
} while (0)

#define GEMM_MAINLOOP()                                                         \
    const int tid  = threadIdx.x;                                               \
    const int w    = tid >> 5;                                                  \
    const int lane = tid & 31;                                                  \
    const int grp  = lane >> 2;                                                 \
    const int t4   = lane & 3;                                                  \
    const int mw   = (w >> 1) * 32;                                             \
    const int nw   = (w & 1) * 64;                                              \
    const int m0   = blockIdx.y * 128;                                          \
    const int n0   = blockIdx.x * 128;                                          \
    const int arow = lane & 15;                                                 \
    const int acol = (lane >> 4) << 3;                                          \
    const int brow = (lane & 7) + ((lane >> 4) << 3);                           \
    const int bcol = ((lane >> 3) & 1) << 3;                                    \
    float acc[2][8][4];                                                         \
    _Pragma("unroll")                                                           \
    for (int mf = 0; mf < 2; mf++)                                              \
        _Pragma("unroll")                                                       \
        for (int nc = 0; nc < 8; nc++)                                          \
            _Pragma("unroll")                                                   \
            for (int j = 0; j < 4; j++) acc[mf][nc][j] = 0.f;                   \
    const int nk = EMBD / 64;                                                   \
    GEMM_STAGE(0, 0);                                                           \
    GEMM_STAGE(1, 64);                                                          \
    for (int i = 0; i < nk; i++) {                                              \
        if (i + 1 < nk) CP_WAIT1(); else CP_WAIT0();                            \
        __syncthreads();                                                        \
        if (i + 2 < nk) { int s_ = (i + 2) % 3; GEMM_STAGE(s_, (i + 2) * 64); } \
        const __half* Ac = smg + (2 * (i % 3)) * GSTAGE;                        \
        const __half* Bc = smg + (2 * (i % 3) + 1) * GSTAGE;                    \
        _Pragma("unroll")                                                       \
        for (int ks = 0; ks < 4; ks++) {                                        \
            unsigned a[2][4];                                                   \
            unsigned bq[2][4];                                                  \
            ldsm4(a[0][0], a[0][1], a[0][2], a[0][3],                           \
                  Ac + (mw + arow) * GP + ks * 16 + acol);                      \
            ldsm4(a[1][0], a[1][1], a[1][2], a[1][3],                           \
                  Ac + (mw + 16 + arow) * GP + ks * 16 + acol);                 \
            ldsm4(bq[0][0], bq[0][1], bq[0][2], bq[0][3],                       \
                  Bc + (nw + brow) * GP + ks * 16 + bcol);                      \
            _Pragma("unroll")                                                   \
            for (int p = 0; p < 4; p++) {                                       \
                if (p < 3)                                                      \
                    ldsm4(bq[(p + 1) & 1][0], bq[(p + 1) & 1][1],               \
                          bq[(p + 1) & 1][2], bq[(p + 1) & 1][3],               \
                          Bc + (nw + (p + 1) * 16 + brow) * GP + ks * 16 + bcol); \
                unsigned* bb = bq[p & 1];                                       \
                mma16(acc[0][2 * p],     a[0][0], a[0][1], a[0][2], a[0][3], bb[0], bb[1]); \
                mma16(acc[1][2 * p],     a[1][0], a[1][1], a[1][2], a[1][3], bb[0], bb[1]); \
                mma16(acc[0][2 * p + 1], a[0][0], a[0][1], a[0][2], a[0][3], bb[2], bb[3]); \
                mma16(acc[1][2 * p + 1], a[1][0], a[1][1], a[1][2], a[1][3], bb[2], bb[3]); \
            }                                                                   \
        }                                                                       \
    }

#define GSMEM (6 * GSTAGE * (int)sizeof(__half))   // 110592 B

// ---------------- QKV GEMM with fused bias + RoPE + scatter epilogue ------------
__global__ __launch_bounds__(256, 2) void gemm_qkv(
    const __half* __restrict__ A, const __half* __restrict__ Bt,
    const float* __restrict__ bias,
    const float* __restrict__ cosb, const float* __restrict__ sinb)
{
    extern __shared__ __half smg[];
    GEMM_MAINLOOP()

    const int region = n0 >> 10;                 // 0=q, 1=k, 2=v
    const int ccbase = (n0 & 1023) + nw;
    __half* dst = (region == 0) ? g_qh : (region == 1) ? g_kh : g_vh;
    const float rsc = (region == 0) ? 0.125f : 1.0f;

#pragma unroll
    for (int mf = 0; mf < 2; mf++) {
#pragma unroll
        for (int hh = 0; hh < 2; hh++) {
            int m = m0 + mw + mf * 16 + hh * 8 + grp;
            int t = m & (SEQ - 1);
            int b = m >> 11;
#pragma unroll
            for (int nc = 0; nc < 8; nc++) {
                int cc = ccbase + nc * 8 + 2 * t4;
                float v0 = acc[mf][nc][2 * hh]     + bias[region * 1024 + cc];
                float v1 = acc[mf][nc][2 * hh + 1] + bias[region * 1024 + cc + 1];
                int hd = cc >> 6;
                int d  = cc & 63;
                size_t o = ((size_t)((b * NHEAD + hd) * SEQ + t)) * HDIM + d;
                if (region < 2) {
                    float c = cosb[t * 32 + (d >> 1)] * rsc;
                    float s = sinb[t * 32 + (d >> 1)] * rsc;
                    *(unsigned*)(dst + o) = packh2(v0 * c - v1 * s, v0 * s + v1 * c);
                } else {
                    *(unsigned*)(dst + o) = packh2(v0, v1);
                }
            }
        }
    }
}

// ---------------- proj GEMM: bias + f32 output ----------------
__global__ __launch_bounds__(256, 2) void gemm_proj(
    const __half* __restrict__ A, const __half* __restrict__ Bt,
    const float* __restrict__ bias, float* __restrict__ C)
{
    extern __shared__ __half smg[];
    GEMM_MAINLOOP()

#pragma unroll
    for (int mf = 0; mf < 2; mf++) {
#pragma unroll
        for (int hh = 0; hh < 2; hh++) {
            int m = m0 + mw + mf * 16 + hh * 8 + grp;
            float* crow = C + (size_t)m * EMBD + n0 + nw;
#pragma unroll
            for (int nc = 0; nc < 8; nc++) {
                int c = nc * 8 + 2 * t4;
                float2 o;
                o.x = acc[mf][nc][2 * hh]     + bias[n0 + nw + c];
                o.y = acc[mf][nc][2 * hh + 1] + bias[n0 + nw + c + 1];
                *(float2*)(crow + c) = o;
            }
        }
    }
}

// ---------------- flash attention (R9): 8 warps x 16 rows, Q frags hoisted ------
// 3-stage K/V ring; V consumed directly from [t][d] via ldmatrix.trans;
// diagonal tiles skip fully-masked mma blocks. Q prescaled by 0.125.
#define AP 72

#define KV_STAGE(s_, k0_) do {                                            \
    __half* Kn_ = Kb0 + (s_) * 64 * AP;                                   \
    __half* Vn_ = Vb0 + (s_) * 64 * AP;                                   \
    _Pragma("unroll")                                                     \
    for (int it_ = 0; it_ < 2; it_++) {                                   \
        int slot_ = tid + it_ * 256;                                      \
        int r_  = slot_ >> 3;                                             \
        int c8_ = (slot_ & 7) << 3;                                       \
        cpa16(Kn_ + r_ * AP + c8_, kp + (size_t)((k0_) + r_) * HDIM + c8_);\
        cpa16(Vn_ + r_ * AP + c8_, vp + (size_t)((k0_) + r_) * HDIM + c8_);\
    }                                                                     \
    CP_COMMIT();                                                          \
} while (0)

__global__ __launch_bounds__(256, 2) void attn_h()
{
    extern __shared__ __half sm[];
    __half* Qs  = sm;                        // 128*72
    __half* Kb0 = sm + 128 * AP;             // 3 x 64*72
    __half* Vb0 = sm + 128 * AP + 3 * 64 * AP;

    const int qt = (int)gridDim.x - 1 - (int)blockIdx.x;
    const int bh = blockIdx.y;
    const int b  = bh >> 4;
    const int h  = bh & 15;
    const __half* qp = g_qh + (size_t)bh * SEQ * HDIM;
    const __half* kp = g_kh + (size_t)bh * SEQ * HDIM;
    const __half* vp = g_vh + (size_t)bh * SEQ * HDIM;
    const int q0 = qt * 128;

    const int tid  = threadIdx.x;
    const int w    = tid >> 5;
    const int lane = tid & 31;
    const int grp  = lane >> 2;
    const int t4   = lane & 3;
    const int mw   = w * 16;

    const int arow = lane & 15;
    const int acol = (lane >> 4) << 3;
    const int brow = (lane & 7) + ((lane >> 4) << 3);
    const int bcol = ((lane >> 3) & 1) << 3;

#pragma unroll
    for (int it = 0; it < 4; it++) {
        int slot = tid + it * 256;
        int r  = slot >> 3;
        int c8 = (slot & 7) << 3;
        cpa16(Qs + r * AP + c8, qp + (size_t)(q0 + r) * HDIM + c8);
    }
    {
#pragma unroll
        for (int it_ = 0; it_ < 2; it_++) {
            int slot_ = tid + it_ * 256;
            int r_  = slot_ >> 3;
            int c8_ = (slot_ & 7) << 3;
            cpa16(Kb0 + r_ * AP + c8_, kp + (size_t)r_ * HDIM + c8_);
            cpa16(Vb0 + r_ * AP + c8_, vp + (size_t)r_ * HDIM + c8_);
        }
        CP_COMMIT();
    }
    KV_STAGE(1, 64);

    float O[8][4];
#pragma unroll
    for (int nc = 0; nc < 8; nc++)
#pragma unroll
        for (int j = 0; j < 4; j++) O[nc][j] = 0.f;
    float mrow[2] = {-INFINITY, -INFINITY};
    float lrow[2] = {0.f, 0.f};

    unsigned qa[4][4];           // hoisted Q fragments (tile-invariant)
    const int rmax = q0 + mw + 15;

    const int kt_max = 2 * qt + 1;
    for (int kt = 0; kt <= kt_max; kt++) {
        const int k0 = kt * 64;
        if (kt < kt_max) CP_WAIT1(); else CP_WAIT0();
        __syncthreads();
        if (kt == 0) {
#pragma unroll
            for (int ks = 0; ks < 4; ks++)
                ldsm4(qa[ks][0], qa[ks][1], qa[ks][2], qa[ks][3],
                      Qs + (mw + arow) * AP + ks * 16 + acol);
        }
        if (kt + 2 <= kt_max) { int s_ = (kt + 2) % 3; KV_STAGE(s_, (kt + 2) * 64); }

        if (k0 <= rmax) {
            const __half* Kb = Kb0 + (kt % 3) * 64 * AP;
            const __half* Vb = Vb0 + (kt % 3) * 64 * AP;

            float S[8][4];
#pragma unroll
            for (int nc = 0; nc < 8; nc++)
#pragma unroll
                for (int j = 0; j < 4; j++) S[nc][j] = 0.f;

#pragma unroll
            for (int ks = 0; ks < 4; ks++) {
#pragma unroll
                for (int nc0 = 0; nc0 < 8; nc0 += 2) {
                    if (k0 + nc0 * 8 <= rmax) {
                        unsigned b0, b1, b2, b3;
                        ldsm4(b0, b1, b2, b3, Kb + (nc0 * 8 + brow) * AP + ks * 16 + bcol);
                        mma16(S[nc0],     qa[ks][0], qa[ks][1], qa[ks][2], qa[ks][3], b0, b1);
                        mma16(S[nc0 + 1], qa[ks][0], qa[ks][1], qa[ks][2], qa[ks][3], b2, b3);
                    }
                }
            }

            if (k0 + 63 > q0 + mw) {
                int r0g = q0 + mw + grp;
                int r1g = r0g + 8;
#pragma unroll
                for (int nc = 0; nc < 8; nc++) {
                    int col = k0 + nc * 8 + 2 * t4;
                    if (col     > r0g) S[nc][0] = -INFINITY;
                    if (col + 1 > r0g) S[nc][1] = -INFINITY;
                    if (col     > r1g) S[nc][2] = -INFINITY;
                    if (col + 1 > r1g) S[nc][3] = -INFINITY;
                }
            }

#pragma unroll
            for (int hh = 0; hh < 2; hh++) {
                float mx = -INFINITY;
#pragma unroll
                for (int nc = 0; nc < 8; nc++)
                    mx = fmaxf(mx, fmaxf(S[nc][2 * hh], S[nc][2 * hh + 1]));
                mx = fmaxf(mx, __shfl_xor_sync(0xffffffffu, mx, 1));
                mx = fmaxf(mx, __shfl_xor_sync(0xffffffffu, mx, 2));

                float mold = mrow[hh];
                float mnew = fmaxf(mold, mx);
                float al   = exp2_poly((mold - mnew) * LOG2E);
                mrow[hh] = mnew;
                float mb = mnew * LOG2E;

                float sum = 0.f;
#pragma unroll
                for (int nc = 0; nc < 8; nc++) {
                    float p0 = exp2_poly(fmaf(S[nc][2 * hh],     LOG2E, -mb));
                    float p1 = exp2_poly(fmaf(S[nc][2 * hh + 1], LOG2E, -mb));
                    S[nc][2 * hh]     = p0;
                    S[nc][2 * hh + 1] = p1;
                    sum += p0 + p1;
                }
                sum += __shfl_xor_sync(0xffffffffu, sum, 1);
                sum += __shfl_xor_sync(0xffffffffu, sum, 2);
                lrow[hh] = lrow[hh] * al + sum;

#pragma unroll
                for (int nc = 0; nc < 8; nc++) {
                    O[nc][2 * hh]     *= al;
                    O[nc][2 * hh + 1] *= al;
                }
            }

#pragma unroll
            for (int ks = 0; ks < 4; ks++) {
                if (k0 + ks * 16 <= rmax) {
                    unsigned a0 = packh2(S[2 * ks][0],     S[2 * ks][1]);
                    unsigned a1 = packh2(S[2 * ks][2],     S[2 * ks][3]);
                    unsigned a2 = packh2(S[2 * ks + 1][0], S[2 * ks + 1][1]);
                    unsigned a3 = packh2(S[2 * ks + 1][2], S[2 * ks + 1][3]);
#pragma unroll
                    for (int nc0 = 0; nc0 < 8; nc0 += 2) {
                        unsigned b0, b1, b2, b3;
                        ldsm4t(b0, b1, b2, b3,
                               Vb + (ks * 16 + arow) * AP + nc0 * 8 + acol);
                        mma16(O[nc0],     a0, a1, a2, a3, b0, b1);
                        mma16(O[nc0 + 1], a0, a1, a2, a3, b2, b3);
                    }
                }
            }
        }
    }

#pragma unroll
    for (int hh = 0; hh < 2; hh++) {
        float inv = 1.f / lrow[hh];
        int row = q0 + mw + hh * 8 + grp;
        size_t base = ((size_t)(b * SEQ + row)) * EMBD + h * HDIM;
#pragma unroll
        for (int nc = 0; nc < 8; nc++) {
            int c = nc * 8 + 2 * t4;
            *(unsigned*)(g_atth + base + c) =
                packh2(O[nc][2 * hh] * inv, O[nc][2 * hh + 1] * inv);
        }
    }
}

// ---------------- launcher ----------------
extern "C" void kernel_launch(void* const* d_in, const int* in_sizes, int n_in,
                              void* d_out, int out_size)
{
    const float* x     = (const float*)d_in[0];
    const float* Wqkv  = (const float*)d_in[1];
    const float* bqkv  = (const float*)d_in[2];
    const float* Wproj = (const float*)d_in[3];
    const float* bproj = (const float*)d_in[4];
    const float* cosb  = (const float*)d_in[5];
    const float* sinb  = (const float*)d_in[6];
    float* out = (float*)d_out;

    void *p_xh, *p_wqkvt, *p_wprojt, *p_atth;
    cudaGetSymbolAddress(&p_xh, g_xh);
    cudaGetSymbolAddress(&p_wqkvt, g_wqkvt);
    cudaGetSymbolAddress(&p_wprojt, g_wprojt);
    cudaGetSymbolAddress(&p_atth, g_atth);

    // 0) fused prepass: conv x + transpose both weights (single launch)
    prep<<<8192, 256>>>(x, Wqkv, Wproj);

    cudaFuncSetAttribute(gemm_qkv, cudaFuncAttributeMaxDynamicSharedMemorySize, GSMEM);
    cudaFuncSetAttribute(gemm_proj, cudaFuncAttributeMaxDynamicSharedMemorySize, GSMEM);

    // 1) QKV GEMM with fused bias + RoPE (+Q prescale) epilogue
    gemm_qkv<<<dim3(QKVN / 128, BT / 128), 256, GSMEM>>>(
        (const __half*)p_xh, (const __half*)p_wqkvt, bqkv, cosb, sinb);

    // 2) causal flash attention
    const int asm_bytes = (128 * AP + 6 * 64 * AP) * sizeof(__half);   // 73728
    cudaFuncSetAttribute(attn_h, cudaFuncAttributeMaxDynamicSharedMemorySize, asm_bytes);
    attn_h<<<dim3(SEQ / 128, BATCH * NHEAD), 256, asm_bytes>>>();

    // 3) output projection
    gemm_proj<<<dim3(EMBD / 128, BT / 128), 256, GSMEM>>>(
        (const __half*)p_atth, (const __half*)p_wprojt, bproj, out);
}

// round 15
// speedup vs baseline: 1.7005x; 1.0980x over previous
#include <cuda_runtime.h>
#include <cuda_fp16.h>
#include <math.h>

// Problem constants
#define BATCH 2
#define SEQ   2048
#define EMBD  1024
#define NHEAD 16
#define HDIM  64
#define BT    (BATCH*SEQ)          // 4096
#define QKVN  (3*EMBD)             // 3072
#define LOG2E 1.4426950408889634f

// ---------------- scratch (device globals) ----------------
__device__ __half g_xh[BT * EMBD];                       // x in half
__device__ __half g_wqkvt[QKVN * EMBD];                  // Wqkv^T [3072][1024] half
__device__ __half g_wprojt[EMBD * EMBD];                 // Wproj^T [1024][1024] half
__device__ __half g_qh[BATCH * NHEAD * SEQ * HDIM];      // [bh][t][d]  (q PRESCALED by 0.125)
__device__ __half g_kh[BATCH * NHEAD * SEQ * HDIM];      // [bh][t][d]
__device__ __half g_vh[BATCH * NHEAD * SEQ * HDIM];      // [bh][t][d]
__device__ __half g_atth[BT * EMBD];                     // attention out, half

// ---------------- helpers ----------------
__device__ __forceinline__ unsigned packh2(float a, float b) {
    __half2 h = __floats2half2_rn(a, b);
    return *(unsigned*)&h;
}

__device__ __forceinline__ void mma16(float* c,
    unsigned a0, unsigned a1, unsigned a2, unsigned a3,
    unsigned b0, unsigned b1)
{
    asm volatile(
        "mma.sync.aligned.m16n8k16.row.col.f32.f16.f16.f32 "
        "{%0,%1,%2,%3},{%4,%5,%6,%7},{%8,%9},{%0,%1,%2,%3};"
        : "+f"(c[0]), "+f"(c[1]), "+f"(c[2]), "+f"(c[3])
        : "r"(a0), "r"(a1), "r"(a2), "r"(a3), "r"(b0), "r"(b1));
}

__device__ __forceinline__ void ldsm4(unsigned& r0, unsigned& r1,
                                      unsigned& r2, unsigned& r3,
                                      const __half* p)
{
    unsigned a = (unsigned)__cvta_generic_to_shared(p);
    asm volatile("ldmatrix.sync.aligned.m8n8.x4.shared.b16 {%0,%1,%2,%3}, [%4];"
        : "=r"(r0), "=r"(r1), "=r"(r2), "=r"(r3) : "r"(a));
}

__device__ __forceinline__ void ldsm4t(unsigned& r0, unsigned& r1,
                                       unsigned& r2, unsigned& r3,
                                       const __half* p)
{
    unsigned a = (unsigned)__cvta_generic_to_shared(p);
    asm volatile("ldmatrix.sync.aligned.m8n8.x4.trans.shared.b16 {%0,%1,%2,%3}, [%4];"
        : "=r"(r0), "=r"(r1), "=r"(r2), "=r"(r3) : "r"(a));
}

// 2^t via FMA-pipe polynomial (no MUFU).
__device__ __forceinline__ float exp2_poly(float t) {
    t = fmaxf(t, -126.0f);
    float z = t + 12582912.0f;
    int   ei = __float_as_int(z) - 0x4B400000;
    float f = t - (float)ei;
    float p = 1.3333558e-3f;
    p = fmaf(p, f, 9.6181291e-3f);
    p = fmaf(p, f, 5.5504109e-2f);
    p = fmaf(p, f, 2.4022651e-1f);
    p = fmaf(p, f, 6.9314718e-1f);
    p = fmaf(p, f, 1.0f);
    return __int_as_float(__float_as_int(p) + (ei << 23));
}

__device__ __forceinline__ void cpa16(__half* dst_smem, const __half* src_gmem) {
    unsigned d = (unsigned)__cvta_generic_to_shared(dst_smem);
    asm volatile("cp.async.cg.shared.global [%0], [%1], 16;" :: "r"(d), "l"(src_gmem));
}
#define CP_COMMIT() asm volatile("cp.async.commit_group;")
#define CP_WAIT0()  asm volatile("cp.async.wait_group 0;" ::: "memory")
#define CP_WAIT1()  asm volatile("cp.async.wait_group 1;" ::: "memory")

// ---------------- fused prepass: conv x -> half, transpose both weights ---------
__global__ __launch_bounds__(256) void prep(
    const float* __restrict__ x,
    const float* __restrict__ Wqkv, const float* __restrict__ Wproj)
{
    __shared__ __half tile[32][33];
    const int bid = blockIdx.x;
    const int tid = threadIdx.x;

    if (bid < 4096) {
        int i = bid * 256 + tid;
        float4 v = *(const float4*)(x + (size_t)i * 4);
        *(uint2*)(g_xh + (size_t)i * 4) = make_uint2(packh2(v.x, v.y), packh2(v.z, v.w));
        return;
    }

    const float* in;
    __half* out;
    int K, N, n0, k0;
    if (bid < 4096 + 3072) {
        int b = bid - 4096;
        in = Wqkv; out = g_wqkvt; K = EMBD; N = QKVN;
        n0 = (b % 96) * 32; k0 = (b / 96) * 32;
    } else {
        int b = bid - 7168;
        in = Wproj; out = g_wprojt; K = EMBD; N = EMBD;
        n0 = (b % 32) * 32; k0 = (b / 32) * 32;
    }
    const int tx = tid & 31;
    const int ty = tid >> 5;
#pragma unroll
    for (int j = 0; j < 4; j++) {
        int kr = ty + j * 8;
        tile[kr][tx] = __float2half(in[(size_t)(k0 + kr) * N + n0 + tx]);
    }
    __syncthreads();
#pragma unroll
    for (int j = 0; j < 4; j++) {
        int nr = ty + j * 8;
        out[(size_t)(n0 + nr) * K + k0 + tx] = tile[tx][nr];
    }
}

// ================= GEMM mainloop: 3-stage cp.async, B-frag prefetch =============
#define GP 72
#define GSTAGE (128 * GP)

#define GEMM_STAGE(s_, k0_) do {                                                \
    __half* As_ = smg + (2 * (s_)) * GSTAGE;                                    \
    __half* Bs_ = smg + (2 * (s_) + 1) * GSTAGE;                                \
    _Pragma("unroll")                                                           \
    for (int it_ = 0; it_ < 4; it_++) {                                         \
        int c_ = tid + it_ * 256;                                               \
        int r_ = c_ >> 3;                                                       \
        int o8_ = (c_ & 7) << 3;                                                \
        cpa16(As_ + r_ * GP + o8_, A + (size_t)(m0 + r_) * EMBD + (k0_) + o8_); \
        cpa16(Bs_ + r_ * GP + o8_, Bt + (size_t)(n0 + r_) * EMBD + (k0_) + o8_);\
    }                                                                           \
    CP_COMMIT();                                                                \
} while (0)

#define GEMM_MAINLOOP()                                                         \
    const int tid  = threadIdx.x;                                               \
    const int w    = tid >> 5;                                                  \
    const int lane = tid & 31;                                                  \
    const int grp  = lane >> 2;                                                 \
    const int t4   = lane & 3;                                                  \
    const int mw   = (w >> 1) * 32;                                             \
    const int nw   = (w & 1) * 64;                                              \
    const int m0   = blockIdx.y * 128;                                          \
    const int n0   = blockIdx.x * 128;                                          \
    const int arow = lane & 15;                                                 \
    const int acol = (lane >> 4) << 3;                                          \
    const int brow = (lane & 7) + ((lane >> 4) << 3);                           \
    const int bcol = ((lane >> 3) & 1) << 3;                                    \
    float acc[2][8][4];                                                         \
    _Pragma("unroll")                                                           \
    for (int mf = 0; mf < 2; mf++)                                              \
        _Pragma("unroll")                                                       \
        for (int nc = 0; nc < 8; nc++)                                          \
            _Pragma("unroll")                                                   \
            for (int j = 0; j < 4; j++) acc[mf][nc][j] = 0.f;                   \
    const int nk = EMBD / 64;                                                   \
    GEMM_STAGE(0, 0);                                                           \
    GEMM_STAGE(1, 64);                                                          \
    for (int i = 0; i < nk; i++) {                                              \
        if (i + 1 < nk) CP_WAIT1(); else CP_WAIT0();                            \
        __syncthreads();                                                        \
        if (i + 2 < nk) { int s_ = (i + 2) % 3; GEMM_STAGE(s_, (i + 2) * 64); } \
        const __half* Ac = smg + (2 * (i % 3)) * GSTAGE;                        \
        const __half* Bc = smg + (2 * (i % 3) + 1) * GSTAGE;                    \
        _Pragma("unroll")                                                       \
        for (int ks = 0; ks < 4; ks++) {                                        \
            unsigned a[2][4];                                                   \
            unsigned bq[2][4];                                                  \
            ldsm4(a[0][0], a[0][1], a[0][2], a[0][3],                           \
                  Ac + (mw + arow) * GP + ks * 16 + acol);                      \
            ldsm4(a[1][0], a[1][1], a[1][2], a[1][3],                           \
                  Ac + (mw + 16 + arow) * GP + ks * 16 + acol);                 \
            ldsm4(bq[0][0], bq[0][1], bq[0][2], bq[0][3],                       \
                  Bc + (nw + brow) * GP + ks * 16 + bcol);                      \
            _Pragma("unroll")                                                   \
            for (int p = 0; p < 4; p++) {                                       \
                if (p < 3)                                                      \
                    ldsm4(bq[(p + 1) & 1][0], bq[(p + 1) & 1][1],               \
                          bq[(p + 1) & 1][2], bq[(p + 1) & 1][3],               \
                          Bc + (nw + (p + 1) * 16 + brow) * GP + ks * 16 + bcol); \
                unsigned* bb = bq[p & 1];                                       \
                mma16(acc[0][2 * p],     a[0][0], a[0][1], a[0][2], a[0][3], bb[0], bb[1]); \
                mma16(acc[1][2 * p],     a[1][0], a[1][1], a[1][2], a[1][3], bb[0], bb[1]); \
                mma16(acc[0][2 * p + 1], a[0][0], a[0][1], a[0][2], a[0][3], bb[2], bb[3]); \
                mma16(acc[1][2 * p + 1], a[1][0], a[1][1], a[1][2], a[1][3], bb[2], bb[3]); \
            }                                                                   \
        }                                                                       \
    }

#define GSMEM (6 * GSTAGE * (int)sizeof(__half))   // 110592 B

// ---------------- QKV GEMM with fused bias + RoPE + scatter epilogue ------------
__global__ __launch_bounds__(256, 2) void gemm_qkv(
    const __half* __restrict__ A, const __half* __restrict__ Bt,
    const float* __restrict__ bias,
    const float* __restrict__ cosb, const float* __restrict__ sinb)
{
    extern __shared__ __half smg[];
    GEMM_MAINLOOP()

    const int region = n0 >> 10;                 // 0=q, 1=k, 2=v
    const int ccbase = (n0 & 1023) + nw;
    __half* dst = (region == 0) ? g_qh : (region == 1) ? g_kh : g_vh;
    const float rsc = (region == 0) ? 0.125f : 1.0f;

#pragma unroll
    for (int mf = 0; mf < 2; mf++) {
#pragma unroll
        for (int hh = 0; hh < 2; hh++) {
            int m = m0 + mw + mf * 16 + hh * 8 + grp;
            int t = m & (SEQ - 1);
            int b = m >> 11;
#pragma unroll
            for (int nc = 0; nc < 8; nc++) {
                int cc = ccbase + nc * 8 + 2 * t4;
                float v0 = acc[mf][nc][2 * hh]     + bias[region * 1024 + cc];
                float v1 = acc[mf][nc][2 * hh + 1] + bias[region * 1024 + cc + 1];
                int hd = cc >> 6;
                int d  = cc & 63;
                size_t o = ((size_t)((b * NHEAD + hd) * SEQ + t)) * HDIM + d;
                if (region < 2) {
                    float c = cosb[t * 32 + (d >> 1)] * rsc;
                    float s = sinb[t * 32 + (d >> 1)] * rsc;
                    *(unsigned*)(dst + o) = packh2(v0 * c - v1 * s, v0 * s + v1 * c);
                } else {
                    *(unsigned*)(dst + o) = packh2(v0, v1);
                }
            }
        }
    }
}

// ---------------- proj GEMM: bias + f32 output ----------------
__global__ __launch_bounds__(256, 2) void gemm_proj(
    const __half* __restrict__ A, const __half* __restrict__ Bt,
    const float* __restrict__ bias, float* __restrict__ C)
{
    extern __shared__ __half smg[];
    GEMM_MAINLOOP()

#pragma unroll
    for (int mf = 0; mf < 2; mf++) {
#pragma unroll
        for (int hh = 0; hh < 2; hh++) {
            int m = m0 + mw + mf * 16 + hh * 8 + grp;
            float* crow = C + (size_t)m * EMBD + n0 + nw;
#pragma unroll
            for (int nc = 0; nc < 8; nc++) {
                int c = nc * 8 + 2 * t4;
                float2 o;
                o.x = acc[mf][nc][2 * hh]     + bias[n0 + nw + c];
                o.y = acc[mf][nc][2 * hh + 1] + bias[n0 + nw + c + 1];
                *(float2*)(crow + c) = o;
            }
        }
    }
}

// ---------------- flash attention: paired q-tiles, single balanced wave ---------
// grid = (8, 32); CTA bx handles qt = 15-bx (long) then qt = bx (short):
// constant 34 tiles per CTA, 256 CTAs -> one wave, no tail imbalance.
#define AP 72

#define KV_STAGE(s_, k0_) do {                                            \
    __half* Kn_ = Kb0 + (s_) * 64 * AP;                                   \
    __half* Vn_ = Vb0 + (s_) * 64 * AP;                                   \
    _Pragma("unroll")                                                     \
    for (int it_ = 0; it_ < 2; it_++) {                                   \
        int slot_ = tid + it_ * 256;                                      \
        int r_  = slot_ >> 3;                                             \
        int c8_ = (slot_ & 7) << 3;                                       \
        cpa16(Kn_ + r_ * AP + c8_, kp + (size_t)((k0_) + r_) * HDIM + c8_);\
        cpa16(Vn_ + r_ * AP + c8_, vp + (size_t)((k0_) + r_) * HDIM + c8_);\
    }                                                                     \
    CP_COMMIT();                                                          \
} while (0)

__global__ __launch_bounds__(256, 2) void attn_h()
{
    extern __shared__ __half sm[];
    __half* Qs  = sm;                        // 128*72
    __half* Kb0 = sm + 128 * AP;             // 3 x 64*72
    __half* Vb0 = sm + 128 * AP + 3 * 64 * AP;

    const int bx = (int)blockIdx.x;          // 0..7
    const int bh = blockIdx.y;
    const int b  = bh >> 4;
    const int h  = bh & 15;
    const __half* qp = g_qh + (size_t)bh * SEQ * HDIM;
    const __half* kp = g_kh + (size_t)bh * SEQ * HDIM;
    const __half* vp = g_vh + (size_t)bh * SEQ * HDIM;

    const int tid  = threadIdx.x;
    const int w    = tid >> 5;
    const int lane = tid & 31;
    const int grp  = lane >> 2;
    const int t4   = lane & 3;
    const int mw   = w * 16;

    const int arow = lane & 15;
    const int acol = (lane >> 4) << 3;
    const int brow = (lane & 7) + ((lane >> 4) << 3);
    const int bcol = ((lane >> 3) & 1) << 3;

    for (int rep = 0; rep < 2; rep++) {
        const int qt = (rep == 0) ? (15 - bx) : bx;   // long tile first
        const int q0 = qt * 128;
        const int kt_max = 2 * qt + 1;

        if (rep == 1) __syncthreads();   // all warps done reading rep-0 smem

        // prologue: stage Q + KV tiles 0,1
#pragma unroll
        for (int it = 0; it < 4; it++) {
            int slot = tid + it * 256;
            int r  = slot >> 3;
            int c8 = (slot & 7) << 3;
            cpa16(Qs + r * AP + c8, qp + (size_t)(q0 + r) * HDIM + c8);
        }
        {
#pragma unroll
            for (int it_ = 0; it_ < 2; it_++) {
                int slot_ = tid + it_ * 256;
                int r_  = slot_ >> 3;
                int c8_ = (slot_ & 7) << 3;
                cpa16(Kb0 + r_ * AP + c8_, kp + (size_t)r_ * HDIM + c8_);
                cpa16(Vb0 + r_ * AP + c8_, vp + (size_t)r_ * HDIM + c8_);
            }
            CP_COMMIT();
        }
        KV_STAGE(1, 64);

        float O[8][4];
#pragma unroll
        for (int nc = 0; nc < 8; nc++)
#pragma unroll
            for (int j = 0; j < 4; j++) O[nc][j] = 0.f;
        float mrow[2] = {-INFINITY, -INFINITY};
        float lrow[2] = {0.f, 0.f};

        unsigned qa[4][4];
        const int rmax = q0 + mw + 15;

        for (int kt = 0; kt <= kt_max; kt++) {
            const int k0 = kt * 64;
            if (kt < kt_max) CP_WAIT1(); else CP_WAIT0();
            __syncthreads();
            if (kt == 0) {
#pragma unroll
                for (int ks = 0; ks < 4; ks++)
                    ldsm4(qa[ks][0], qa[ks][1], qa[ks][2], qa[ks][3],
                          Qs + (mw + arow) * AP + ks * 16 + acol);
            }
            if (kt + 2 <= kt_max) { int s_ = (kt + 2) % 3; KV_STAGE(s_, (kt + 2) * 64); }

            if (k0 <= rmax) {
                const __half* Kb = Kb0 + (kt % 3) * 64 * AP;
                const __half* Vb = Vb0 + (kt % 3) * 64 * AP;

                float S[8][4];
#pragma unroll
                for (int nc = 0; nc < 8; nc++)
#pragma unroll
                    for (int j = 0; j < 4; j++) S[nc][j] = 0.f;

#pragma unroll
                for (int ks = 0; ks < 4; ks++) {
#pragma unroll
                    for (int nc0 = 0; nc0 < 8; nc0 += 2) {
                        if (k0 + nc0 * 8 <= rmax) {
                            unsigned b0, b1, b2, b3;
                            ldsm4(b0, b1, b2, b3, Kb + (nc0 * 8 + brow) * AP + ks * 16 + bcol);
                            mma16(S[nc0],     qa[ks][0], qa[ks][1], qa[ks][2], qa[ks][3], b0, b1);
                            mma16(S[nc0 + 1], qa[ks][0], qa[ks][1], qa[ks][2], qa[ks][3], b2, b3);
                        }
                    }
                }

                if (k0 + 63 > q0 + mw) {
                    int r0g = q0 + mw + grp;
                    int r1g = r0g + 8;
#pragma unroll
                    for (int nc = 0; nc < 8; nc++) {
                        int col = k0 + nc * 8 + 2 * t4;
                        if (col     > r0g) S[nc][0] = -INFINITY;
                        if (col + 1 > r0g) S[nc][1] = -INFINITY;
                        if (col     > r1g) S[nc][2] = -INFINITY;
                        if (col + 1 > r1g) S[nc][3] = -INFINITY;
                    }
                }

#pragma unroll
                for (int hh = 0; hh < 2; hh++) {
                    float mx = -INFINITY;
#pragma unroll
                    for (int nc = 0; nc < 8; nc++)
                        mx = fmaxf(mx, fmaxf(S[nc][2 * hh], S[nc][2 * hh + 1]));
                    mx = fmaxf(mx, __shfl_xor_sync(0xffffffffu, mx, 1));
                    mx = fmaxf(mx, __shfl_xor_sync(0xffffffffu, mx, 2));

                    float mold = mrow[hh];
                    float mnew = fmaxf(mold, mx);
                    float al   = exp2_poly((mold - mnew) * LOG2E);
                    mrow[hh] = mnew;
                    float mb = mnew * LOG2E;

                    float sum = 0.f;
#pragma unroll
                    for (int nc = 0; nc < 8; nc++) {
                        float p0 = exp2_poly(fmaf(S[nc][2 * hh],     LOG2E, -mb));
                        float p1 = exp2_poly(fmaf(S[nc][2 * hh + 1], LOG2E, -mb));
                        S[nc][2 * hh]     = p0;
                        S[nc][2 * hh + 1] = p1;
                        sum += p0 + p1;
                    }
                    sum += __shfl_xor_sync(0xffffffffu, sum, 1);
                    sum += __shfl_xor_sync(0xffffffffu, sum, 2);
                    lrow[hh] = lrow[hh] * al + sum;

#pragma unroll
                    for (int nc = 0; nc < 8; nc++) {
                        O[nc][2 * hh]     *= al;
                        O[nc][2 * hh + 1] *= al;
                    }
                }

#pragma unroll
                for (int ks = 0; ks < 4; ks++) {
                    if (k0 + ks * 16 <= rmax) {
                        unsigned a0 = packh2(S[2 * ks][0],     S[2 * ks][1]);
                        unsigned a1 = packh2(S[2 * ks][2],     S[2 * ks][3]);
                        unsigned a2 = packh2(S[2 * ks + 1][0], S[2 * ks + 1][1]);
                        unsigned a3 = packh2(S[2 * ks + 1][2], S[2 * ks + 1][3]);
#pragma unroll
                        for (int nc0 = 0; nc0 < 8; nc0 += 2) {
                            unsigned b0, b1, b2, b3;
                            ldsm4t(b0, b1, b2, b3,
                                   Vb + (ks * 16 + arow) * AP + nc0 * 8 + acol);
                            mma16(O[nc0],     a0, a1, a2, a3, b0, b1);
                            mma16(O[nc0 + 1], a0, a1, a2, a3, b2, b3);
                        }
                    }
                }
            }
        }

        // epilogue for this q-tile
#pragma unroll
        for (int hh = 0; hh < 2; hh++) {
            float inv = 1.f / lrow[hh];
            int row = q0 + mw + hh * 8 + grp;
            size_t base = ((size_t)(b * SEQ + row)) * EMBD + h * HDIM;
#pragma unroll
            for (int nc = 0; nc < 8; nc++) {
                int c = nc * 8 + 2 * t4;
                *(unsigned*)(g_atth + base + c) =
                    packh2(O[nc][2 * hh] * inv, O[nc][2 * hh + 1] * inv);
            }
        }
    }
}

// ---------------- launcher ----------------
extern "C" void kernel_launch(void* const* d_in, const int* in_sizes, int n_in,
                              void* d_out, int out_size)
{
    const float* x     = (const float*)d_in[0];
    const float* Wqkv  = (const float*)d_in[1];
    const float* bqkv  = (const float*)d_in[2];
    const float* Wproj = (const float*)d_in[3];
    const float* bproj = (const float*)d_in[4];
    const float* cosb  = (const float*)d_in[5];
    const float* sinb  = (const float*)d_in[6];
    float* out = (float*)d_out;

    void *p_xh, *p_wqkvt, *p_wprojt, *p_atth;
    cudaGetSymbolAddress(&p_xh, g_xh);
    cudaGetSymbolAddress(&p_wqkvt, g_wqkvt);
    cudaGetSymbolAddress(&p_wprojt, g_wprojt);
    cudaGetSymbolAddress(&p_atth, g_atth);

    // 0) fused prepass: conv x + transpose both weights (single launch)
    prep<<<8192, 256>>>(x, Wqkv, Wproj);

    cudaFuncSetAttribute(gemm_qkv, cudaFuncAttributeMaxDynamicSharedMemorySize, GSMEM);
    cudaFuncSetAttribute(gemm_proj, cudaFuncAttributeMaxDynamicSharedMemorySize, GSMEM);

    // 1) QKV GEMM with fused bias + RoPE (+Q prescale) epilogue
    gemm_qkv<<<dim3(QKVN / 128, BT / 128), 256, GSMEM>>>(
        (const __half*)p_xh, (const __half*)p_wqkvt, bqkv, cosb, sinb);

    // 2) causal flash attention (paired q-tiles, balanced single wave)
    const int asm_bytes = (128 * AP + 6 * 64 * AP) * sizeof(__half);   // 73728
    cudaFuncSetAttribute(attn_h, cudaFuncAttributeMaxDynamicSharedMemorySize, asm_bytes);
    attn_h<<<dim3(8, BATCH * NHEAD), 256, asm_bytes>>>();

    // 3) output projection
    gemm_proj<<<dim3(EMBD / 128, BT / 128), 256, GSMEM>>>(
        (const __half*)p_atth, (const __half*)p_wprojt, bproj, out);
}